// round 2
// baseline (speedup 1.0000x reference)
#include <cuda_runtime.h>
#include <math.h>

// Problem constants
#define BQ 32
#define DAQ 2
#define WQ 64
#define MQ 16
#define LQ 8192
#define NBQ 32          // 2*MODES (interleaved cos/sin channels)
#define KSPL 16         // K-split for forward DFT

typedef unsigned long long ull;

// Scratch (device globals: allocation-free rule)
__device__ float g_hA[BQ * WQ * LQ];            // 64 MB
__device__ float g_hB[BQ * WQ * LQ];            // 64 MB
__device__ float g_T[LQ * NBQ];                 // basis [l][n]  (1 MB)
__device__ float g_Tt[NBQ * LQ];                // basis transposed [n][l] (1 MB)
__device__ float g_Fpart[BQ * KSPL * WQ * NBQ]; // forward DFT partials (4 MB)
__device__ float g_coef[BQ * WQ * NBQ];         // inverse-DFT coefficients (1 MB)

__device__ __forceinline__ float gelu_exact(float v) {
    return 0.5f * v * (1.0f + erff(v * 0.70710678118654752440f));
}

// ---- packed f32x2 helpers (Blackwell FFMA2 path, PTX-only) --------------
__device__ __forceinline__ ull pack2(float x, float y) {
    ull d; asm("mov.b64 %0, {%1, %2};" : "=l"(d) : "f"(x), "f"(y)); return d;
}
__device__ __forceinline__ void unpack2(float& x, float& y, ull d) {
    asm("mov.b64 {%0, %1}, %2;" : "=f"(x), "=f"(y) : "l"(d));
}
__device__ __forceinline__ ull fma2(ull a, ull b, ull c) {
    ull d; asm("fma.rn.f32x2 %0, %1, %2, %3;" : "=l"(d) : "l"(a), "l"(b), "l"(c));
    return d;
}

// ---------------------------------------------------------------------------
// Basis tables. T[l][2k]=cos(2pi k l/L), T[l][2k+1]=sin(...); Tt = transpose.
// Mapping: k = idx>>13, l = idx&8191 -> Tt writes coalesced.
// ---------------------------------------------------------------------------
__global__ void build_table_kernel() {
    int idx = blockIdx.x * blockDim.x + threadIdx.x;  // 131072
    int k = idx >> 13;
    int l = idx & (LQ - 1);
    int m = (k * l) & (LQ - 1);
    float ang = (float)m * (6.283185307179586476925f / (float)LQ);
    float s, c;
    sincosf(ang, &s, &c);
    g_T[l * NBQ + 2 * k]     = c;
    g_T[l * NBQ + 2 * k + 1] = s;
    g_Tt[(2 * k) * LQ + l]     = c;
    g_Tt[(2 * k + 1) * LQ + l] = s;
}

// ---------------------------------------------------------------------------
// Lifting: h[b,w,l] = Pw[w,0]*x[b,0,l] + Pw[w,1]*x[b,1,l] + Pb[w]
// ---------------------------------------------------------------------------
__global__ void lift_kernel(const float* __restrict__ x,
                            const float* __restrict__ Pw,
                            const float* __restrict__ Pb,
                            float* __restrict__ h) {
    int idx = blockIdx.x * 256 + threadIdx.x;
    int l = idx & (LQ - 1);
    int w = (idx >> 13) & 63;
    int b = idx >> 19;
    float x0 = x[(b * 2 + 0) * LQ + l];
    float x1 = x[(b * 2 + 1) * LQ + l];
    h[idx] = Pw[2 * w] * x0 + Pw[2 * w + 1] * x1 + Pb[w];
}

// ---------------------------------------------------------------------------
// Forward DFT (16 modes) tiled GEMM with f32x2 accumulators.
//   Fpart[b, ks, c, n] = sum over 512-l chunk of h[b,c,l] * T[l,n]
// Grid (B, KSPL=16); 256 threads; smem Ht[64][129] + Tt[128][32].
// ---------------------------------------------------------------------------
__global__ void __launch_bounds__(256) fwd_dft_kernel(const float* __restrict__ h) {
    extern __shared__ float sm[];
    float* Ht = sm;                // 64 * 129
    float* Tt = sm + 64 * 129;     // 128 * 32
    int b = blockIdx.x;
    int ks = blockIdx.y;
    int t = threadIdx.x;
    int cc = t & 31;
    int nq = (t >> 5) << 2;        // 0,4,...,28
    ull p0 = 0, p1 = 0, p2 = 0, p3 = 0;  // (n,n+1)x(c0,c1) packed pairs; 0 == (0.f,0.f)
    const int lbase = ks * (LQ / KSPL);  // 512

    for (int chk = 0; chk < 4; chk++) {
        int l0 = lbase + chk * 128;
        __syncthreads();
#pragma unroll
        for (int j = 0; j < 32; j++) {
            int idx = t + 256 * j;       // 8192 floats
            int c = idx >> 7, l = idx & 127;
            Ht[c * 129 + l] = h[(b * 64 + c) * LQ + l0 + l];
        }
#pragma unroll
        for (int j = 0; j < 4; j++) {
            int idx = t + 256 * j;       // 1024 float4 = 128x32 floats
            ((float4*)Tt)[idx] = ((const float4*)g_T)[l0 * 8 + idx];
        }
        __syncthreads();
#pragma unroll 4
        for (int l = 0; l < 128; l++) {
            float a0 = Ht[cc * 129 + l];
            float a1 = Ht[(cc + 32) * 129 + l];
            ull d0 = pack2(a0, a0);
            ull d1 = pack2(a1, a1);
            ulonglong2 bv = *(const ulonglong2*)(Tt + l * 32 + nq);
            p0 = fma2(bv.x, d0, p0);
            p1 = fma2(bv.y, d0, p1);
            p2 = fma2(bv.x, d1, p2);
            p3 = fma2(bv.y, d1, p3);
        }
    }
    int base0 = ((b * KSPL + ks) * 64 + cc) * NBQ + nq;
    int base1 = ((b * KSPL + ks) * 64 + cc + 32) * NBQ + nq;
    *(ull*)(g_Fpart + base0)     = p0;
    *(ull*)(g_Fpart + base0 + 2) = p1;
    *(ull*)(g_Fpart + base1)     = p2;
    *(ull*)(g_Fpart + base1 + 2) = p3;
}

// ---------------------------------------------------------------------------
// Mode mixing + irfft coefficient prep. Grid 512 = (b,k); 256 threads:
// o = t&63, q = t>>6 handles a 16-wide i-slice; smem reduce.
// ---------------------------------------------------------------------------
__global__ void __launch_bounds__(256) mode_mix_kernel(const float* __restrict__ kwr,
                                                       const float* __restrict__ kwi, int ib) {
    int b = blockIdx.x >> 4;
    int k = blockIdx.x & 15;
    int t = threadIdx.x;
    int o = t & 63;
    int q = t >> 6;
    __shared__ float Hr[64], Hs[64];
    __shared__ float arS[4][64], aiS[4][64];
    if (t < 64) {
        float hr = 0.f, hs = 0.f;
#pragma unroll
        for (int p = 0; p < KSPL; p++) {
            hr += g_Fpart[((b * KSPL + p) * 64 + t) * NBQ + 2 * k];
            hs += g_Fpart[((b * KSPL + p) * 64 + t) * NBQ + 2 * k + 1];
        }
        Hr[t] = hr;
        Hs[t] = hs;
    }
    __syncthreads();
    const float* wr = kwr + (((size_t)ib * 16 + k) * 64 + o) * 64 + q * 16;
    const float* wi = kwi + (((size_t)ib * 16 + k) * 64 + o) * 64 + q * 16;
    float ar = 0.f, ai = 0.f;
#pragma unroll
    for (int i = 0; i < 16; i++) {
        float xr = Hr[q * 16 + i];
        float xi = -Hs[q * 16 + i];
        float wrv = wr[i], wiv = wi[i];
        ar += wrv * xr - wiv * xi;
        ai += wrv * xi + wiv * xr;
    }
    arS[q][o] = ar;
    aiS[q][o] = ai;
    __syncthreads();
    if (t < 64) {
        float A = arS[0][t] + arS[1][t] + arS[2][t] + arS[3][t];
        float I = aiS[0][t] + aiS[1][t] + aiS[2][t] + aiS[3][t];
        const float invL = 1.0f / (float)LQ;
        float cC, cS;
        if (k == 0) { cC = A * invL;        cS = 0.f; }
        else        { cC = 2.f * A * invL;  cS = -2.f * I * invL; }
        g_coef[(b * 64 + t) * NBQ + 2 * k]     = cC;
        g_coef[(b * 64 + t) * NBQ + 2 * k + 1] = cS;
    }
}

// ---------------------------------------------------------------------------
// Fused inverse-DFT + 1x1 conv + bias + exact GELU, f32x2 throughout.
// Grid (L/256, B), 256 threads. Thread (og=t>>7, ls=t&127) owns l-pair
// l0 = tile + 2*ls and 32 outputs og*32..+31 packed as 16 output-pairs.
// 96 "channels": 0..31 = basis rows (g_Tt), 32..95 = h rows. Per channel:
// one coalesced LDG.64 (v at l0,l0+1), dup-packs, 8 LDS.128 of weight pairs,
// 32 FFMA2.
// ---------------------------------------------------------------------------
__global__ void __launch_bounds__(256) fused_block_kernel(
    const float* __restrict__ hin, float* __restrict__ hout,
    const float* __restrict__ cw, const float* __restrict__ cb, int ib) {
    __shared__ __align__(16) float wS[96 * 64];   // rows: 32 coef + 64 conv, [ch][o]
    __shared__ float biasS[64];
    int b = blockIdx.y;
    int t = threadIdx.x;
    int og = t >> 7;
    int l0 = blockIdx.x * 256 + ((t & 127) << 1);

#pragma unroll
    for (int j = 0; j < 8; j++) {           // 2048 coef
        int idx = t + 256 * j;
        int o = idx >> 5, n = idx & 31;
        wS[n * 64 + o] = g_coef[(b * 64 + o) * NBQ + n];
    }
#pragma unroll
    for (int j = 0; j < 16; j++) {          // 4096 conv
        int idx = t + 256 * j;
        int o = idx >> 6, c = idx & 63;
        wS[(32 + c) * 64 + o] = cw[((size_t)ib * 64 + o) * 64 + c];
    }
    if (t < 64) biasS[t] = cb[ib * 64 + t];
    __syncthreads();

    ull accA[16], accB[16];                 // [output-pair] for l0 / l0+1
    const float* brow = biasS + og * 32;
#pragma unroll
    for (int j = 0; j < 16; j++) {
        ull bv = pack2(brow[2 * j], brow[2 * j + 1]);
        accA[j] = bv;
        accB[j] = bv;
    }

    const float* wbase = wS + og * 32;

    // basis channels
    const float* tp = g_Tt + l0;
#pragma unroll 4
    for (int ch = 0; ch < 32; ch++) {
        float2 v = *(const float2*)(tp + (size_t)ch * LQ);
        ull dx = pack2(v.x, v.x);
        ull dy = pack2(v.y, v.y);
        const float* wrow = wbase + ch * 64;
#pragma unroll
        for (int q = 0; q < 8; q++) {
            ulonglong2 w2 = *(const ulonglong2*)(wrow + 4 * q);
            accA[2 * q]     = fma2(w2.x, dx, accA[2 * q]);
            accB[2 * q]     = fma2(w2.x, dy, accB[2 * q]);
            accA[2 * q + 1] = fma2(w2.y, dx, accA[2 * q + 1]);
            accB[2 * q + 1] = fma2(w2.y, dy, accB[2 * q + 1]);
        }
    }
    // conv channels
    const float* hp = hin + (size_t)(b * 64) * LQ + l0;
#pragma unroll 4
    for (int c = 0; c < 64; c++) {
        float2 v = *(const float2*)(hp + (size_t)c * LQ);
        ull dx = pack2(v.x, v.x);
        ull dy = pack2(v.y, v.y);
        const float* wrow = wbase + (32 + c) * 64;
#pragma unroll
        for (int q = 0; q < 8; q++) {
            ulonglong2 w2 = *(const ulonglong2*)(wrow + 4 * q);
            accA[2 * q]     = fma2(w2.x, dx, accA[2 * q]);
            accB[2 * q]     = fma2(w2.x, dy, accB[2 * q]);
            accA[2 * q + 1] = fma2(w2.y, dx, accA[2 * q + 1]);
            accB[2 * q + 1] = fma2(w2.y, dy, accB[2 * q + 1]);
        }
    }

#pragma unroll
    for (int j = 0; j < 16; j++) {
        float a0, a1, c0, c1;
        unpack2(a0, a1, accA[j]);
        unpack2(c0, c1, accB[j]);
        int o = og * 32 + 2 * j;
        *(float2*)&hout[(size_t)(b * 64 + o) * LQ + l0] =
            make_float2(gelu_exact(a0), gelu_exact(c0));
        *(float2*)&hout[(size_t)(b * 64 + o + 1) * LQ + l0] =
            make_float2(gelu_exact(a1), gelu_exact(c1));
    }
}

// ---------------------------------------------------------------------------
// Projection: out[b,0,l] = sum_c Qw[c]*h[b,c,l] + Qb
// ---------------------------------------------------------------------------
__global__ void proj_kernel(const float* __restrict__ h,
                            const float* __restrict__ Qw,
                            const float* __restrict__ Qb,
                            float* __restrict__ out) {
    int b = blockIdx.y;
    int l = blockIdx.x * 256 + threadIdx.x;
    float acc = Qb[0];
#pragma unroll
    for (int c = 0; c < 64; c++)
        acc += Qw[c] * h[(b * 64 + c) * LQ + l];
    out[b * LQ + l] = acc;
}

// ---------------------------------------------------------------------------
extern "C" void kernel_launch(void* const* d_in, const int* in_sizes, int n_in,
                              void* d_out, int out_size) {
    const float* x   = (const float*)d_in[0];
    const float* Pw  = (const float*)d_in[1];
    const float* Pb  = (const float*)d_in[2];
    const float* kwr = (const float*)d_in[3];
    const float* kwi = (const float*)d_in[4];
    const float* cw  = (const float*)d_in[5];
    const float* cb  = (const float*)d_in[6];
    const float* Qw  = (const float*)d_in[7];
    const float* Qb  = (const float*)d_in[8];
    float* out = (float*)d_out;

    float *hA = nullptr, *hB = nullptr;
    cudaGetSymbolAddress((void**)&hA, g_hA);
    cudaGetSymbolAddress((void**)&hB, g_hB);

    const int FWD_SMEM = (64 * 129 + 128 * 32) * 4;   // 49408 B
    cudaFuncSetAttribute(fwd_dft_kernel,
                         cudaFuncAttributeMaxDynamicSharedMemorySize, FWD_SMEM);

    build_table_kernel<<<(LQ * MQ) / 256, 256>>>();
    lift_kernel<<<(BQ * WQ * LQ) / 256, 256>>>(x, Pw, Pb, hA);

    float* cur = hA;
    float* nxt = hB;
    for (int ib = 0; ib < 4; ib++) {
        fwd_dft_kernel<<<dim3(BQ, KSPL), 256, FWD_SMEM>>>(cur);
        mode_mix_kernel<<<BQ * MQ, 256>>>(kwr, kwi, ib);
        fused_block_kernel<<<dim3(LQ / 256, BQ), 256>>>(cur, nxt, cw, cb, ib);
        float* tmp = cur; cur = nxt; nxt = tmp;
    }
    proj_kernel<<<dim3(LQ / 256, BQ), 256>>>(cur, Qw, Qb, out);
}

// round 3
// speedup vs baseline: 1.4937x; 1.4937x over previous
#include <cuda_runtime.h>
#include <math.h>

// Problem constants
#define BQ 32
#define DAQ 2
#define WQ 64
#define MQ 16
#define LQ 8192
#define NBQ 32          // 2*MODES (interleaved cos/sin channels)
#define KSPL 16         // K-split for forward DFT

// Scratch (device globals: allocation-free rule)
__device__ float g_hA[BQ * WQ * LQ];            // 64 MB
__device__ float g_hB[BQ * WQ * LQ];            // 64 MB
__device__ float g_T[LQ * NBQ];                 // basis [l][n]  (1 MB)
__device__ float g_Tt[NBQ * LQ];                // basis transposed [n][l] (1 MB)
__device__ float g_Fpart[BQ * KSPL * WQ * NBQ]; // forward DFT partials (4 MB)
__device__ float g_coef[BQ * WQ * NBQ];         // inverse-DFT coefficients (1 MB)

__device__ __forceinline__ float gelu_exact(float v) {
    return 0.5f * v * (1.0f + erff(v * 0.70710678118654752440f));
}

// ---------------------------------------------------------------------------
// Basis tables. T[l][2k]=cos(2pi k l/L), T[l][2k+1]=sin(...); Tt = transpose.
// ---------------------------------------------------------------------------
__global__ void build_table_kernel() {
    int idx = blockIdx.x * blockDim.x + threadIdx.x;  // 131072
    int k = idx >> 13;
    int l = idx & (LQ - 1);
    int m = (k * l) & (LQ - 1);
    float ang = (float)m * (6.283185307179586476925f / (float)LQ);
    float s, c;
    sincosf(ang, &s, &c);
    g_T[l * NBQ + 2 * k]     = c;
    g_T[l * NBQ + 2 * k + 1] = s;
    g_Tt[(2 * k) * LQ + l]     = c;
    g_Tt[(2 * k + 1) * LQ + l] = s;
}

// ---------------------------------------------------------------------------
// Lifting: h[b,w,l] = Pw[w,0]*x[b,0,l] + Pw[w,1]*x[b,1,l] + Pb[w]
// ---------------------------------------------------------------------------
__global__ void lift_kernel(const float* __restrict__ x,
                            const float* __restrict__ Pw,
                            const float* __restrict__ Pb,
                            float* __restrict__ h) {
    int idx = blockIdx.x * 256 + threadIdx.x;
    int l = idx & (LQ - 1);
    int w = (idx >> 13) & 63;
    int b = idx >> 19;
    float x0 = x[(b * 2 + 0) * LQ + l];
    float x1 = x[(b * 2 + 1) * LQ + l];
    h[idx] = Pw[2 * w] * x0 + Pw[2 * w + 1] * x1 + Pb[w];
}

// ---------------------------------------------------------------------------
// Forward DFT (16 modes) tiled GEMM.
//   Fpart[b, ks, c, n] = sum over 512-l chunk of h[b,c,l] * T[l,n]
// Grid (B, KSPL=16); 128 threads. Thread: cc=t&31 owns c in {cc, cc+32};
// ng=t>>5 owns n in [8ng, 8ng+8). 16 accumulators; per l-step:
// 2 conflict-free LDS + 2 broadcast LDS.128 -> 16 FFMA.
// ---------------------------------------------------------------------------
__global__ void __launch_bounds__(128) fwd_dft_kernel(const float* __restrict__ h) {
    extern __shared__ float sm[];
    float* Ht = sm;                // 64 * 129
    float* Tt = sm + 64 * 129;     // 128 * 32
    int b = blockIdx.x;
    int ks = blockIdx.y;
    int t = threadIdx.x;
    int cc = t & 31;
    int nq = (t >> 5) << 3;        // 0,8,16,24
    float acc0[8] = {0.f, 0.f, 0.f, 0.f, 0.f, 0.f, 0.f, 0.f};
    float acc1[8] = {0.f, 0.f, 0.f, 0.f, 0.f, 0.f, 0.f, 0.f};
    const int lbase = ks * (LQ / KSPL);  // 512

    for (int chk = 0; chk < 4; chk++) {
        int l0 = lbase + chk * 128;
        __syncthreads();
#pragma unroll
        for (int j = 0; j < 64; j++) {
            int idx = t + 128 * j;       // 8192 floats
            int c = idx >> 7, l = idx & 127;
            Ht[c * 129 + l] = h[(b * 64 + c) * LQ + l0 + l];
        }
#pragma unroll
        for (int j = 0; j < 8; j++) {
            int idx = t + 128 * j;       // 1024 float4 = 128x32 floats
            ((float4*)Tt)[idx] = ((const float4*)g_T)[l0 * 8 + idx];
        }
        __syncthreads();
#pragma unroll 4
        for (int l = 0; l < 128; l++) {
            float a0 = Ht[cc * 129 + l];
            float a1 = Ht[(cc + 32) * 129 + l];
            float4 bv0 = *(float4*)(Tt + l * 32 + nq);       // broadcast
            float4 bv1 = *(float4*)(Tt + l * 32 + nq + 4);   // broadcast
            acc0[0] += a0 * bv0.x; acc0[1] += a0 * bv0.y;
            acc0[2] += a0 * bv0.z; acc0[3] += a0 * bv0.w;
            acc0[4] += a0 * bv1.x; acc0[5] += a0 * bv1.y;
            acc0[6] += a0 * bv1.z; acc0[7] += a0 * bv1.w;
            acc1[0] += a1 * bv0.x; acc1[1] += a1 * bv0.y;
            acc1[2] += a1 * bv0.z; acc1[3] += a1 * bv0.w;
            acc1[4] += a1 * bv1.x; acc1[5] += a1 * bv1.y;
            acc1[6] += a1 * bv1.z; acc1[7] += a1 * bv1.w;
        }
    }
    int base0 = ((b * KSPL + ks) * 64 + cc) * NBQ + nq;
    int base1 = ((b * KSPL + ks) * 64 + cc + 32) * NBQ + nq;
    *(float4*)(g_Fpart + base0)     = make_float4(acc0[0], acc0[1], acc0[2], acc0[3]);
    *(float4*)(g_Fpart + base0 + 4) = make_float4(acc0[4], acc0[5], acc0[6], acc0[7]);
    *(float4*)(g_Fpart + base1)     = make_float4(acc1[0], acc1[1], acc1[2], acc1[3]);
    *(float4*)(g_Fpart + base1 + 4) = make_float4(acc1[4], acc1[5], acc1[6], acc1[7]);
}

// ---------------------------------------------------------------------------
// Mode mixing + irfft coefficient prep. Grid 512 = (b,k); 64 threads = o.
// Weights staged coalesced into padded smem (stride 65 -> conflict-free).
// ---------------------------------------------------------------------------
__global__ void __launch_bounds__(64) mode_mix_kernel(const float* __restrict__ kwr,
                                                      const float* __restrict__ kwi, int ib) {
    int b = blockIdx.x >> 4;
    int k = blockIdx.x & 15;
    int o = threadIdx.x;
    __shared__ float Hr[64], Hs[64];
    __shared__ float wrS[64 * 65], wiS[64 * 65];

    float hr = 0.f, hs = 0.f;
#pragma unroll
    for (int p = 0; p < KSPL; p++) {
        hr += g_Fpart[((b * KSPL + p) * 64 + o) * NBQ + 2 * k];
        hs += g_Fpart[((b * KSPL + p) * 64 + o) * NBQ + 2 * k + 1];
    }
    Hr[o] = hr;
    Hs[o] = hs;

    const float* wrG = kwr + ((size_t)ib * 16 + k) * 4096;
    const float* wiG = kwi + ((size_t)ib * 16 + k) * 4096;
#pragma unroll
    for (int j = 0; j < 64; j++) {          // coalesced: row j, col o
        wrS[j * 65 + o] = wrG[j * 64 + o];
        wiS[j * 65 + o] = wiG[j * 64 + o];
    }
    __syncthreads();

    float ar = 0.f, ai = 0.f;
#pragma unroll 8
    for (int i = 0; i < 64; i++) {
        float xr = Hr[i];
        float xi = -Hs[i];
        float wrv = wrS[o * 65 + i];
        float wiv = wiS[o * 65 + i];
        ar += wrv * xr - wiv * xi;
        ai += wrv * xi + wiv * xr;
    }
    const float invL = 1.0f / (float)LQ;
    float cC, cS;
    if (k == 0) { cC = ar * invL;        cS = 0.f; }
    else        { cC = 2.f * ar * invL;  cS = -2.f * ai * invL; }
    g_coef[(b * 64 + o) * NBQ + 2 * k]     = cC;
    g_coef[(b * 64 + o) * NBQ + 2 * k + 1] = cS;
}

// ---------------------------------------------------------------------------
// Fused inverse-DFT + 1x1 conv + bias + exact GELU as a register-tiled GEMM:
//   C[o=64, l-tile=128] = W[96,64]^T * A[96, l-tile],
// A rows 0..31 = basis (g_Tt), rows 32..95 = hin channels.
// 256 threads: og = t>>5 owns o in [8og, 8og+8); lg = t&31 owns l-quad
// l = l0 + 4*lg. 32 accumulators; per k-step: 1 coalesced LDG.128 (A)
// + 2 broadcast LDS.128 (W) -> 32 FFMA.
// ---------------------------------------------------------------------------
__global__ void __launch_bounds__(256) fused_block_kernel(
    const float* __restrict__ hin, float* __restrict__ hout,
    const float* __restrict__ cw, const float* __restrict__ cb, int ib) {
    __shared__ __align__(16) float wS[96 * 64];   // [ch][o]: 32 coef + 64 conv
    __shared__ float biasS[64];
    int b = blockIdx.y;
    int t = threadIdx.x;
    int og = t >> 5;                 // 0..7
    int lg = t & 31;
    int l = blockIdx.x * 128 + lg * 4;

#pragma unroll
    for (int j = 0; j < 8; j++) {           // 2048 coef
        int idx = t + 256 * j;
        int o = idx >> 5, n = idx & 31;
        wS[n * 64 + o] = g_coef[(b * 64 + o) * NBQ + n];
    }
#pragma unroll
    for (int j = 0; j < 16; j++) {          // 4096 conv
        int idx = t + 256 * j;
        int o = idx >> 6, c = idx & 63;
        wS[(32 + c) * 64 + o] = cw[((size_t)ib * 64 + o) * 64 + c];
    }
    if (t < 64) biasS[t] = cb[ib * 64 + t];
    __syncthreads();

    float4 acc[8];
#pragma unroll
    for (int j = 0; j < 8; j++) {
        float bv = biasS[og * 8 + j];
        acc[j] = make_float4(bv, bv, bv, bv);
    }

    const float* wbase = wS + og * 8;

    // basis channels (g_Tt: L2-resident, shared across all b)
    const float* tp = g_Tt + l;
#pragma unroll 4
    for (int ch = 0; ch < 32; ch++) {
        float4 av = *(const float4*)(tp + (size_t)ch * LQ);
        float4 w0 = *(const float4*)(wbase + ch * 64);       // broadcast
        float4 w1 = *(const float4*)(wbase + ch * 64 + 4);   // broadcast
        acc[0].x += w0.x * av.x; acc[0].y += w0.x * av.y; acc[0].z += w0.x * av.z; acc[0].w += w0.x * av.w;
        acc[1].x += w0.y * av.x; acc[1].y += w0.y * av.y; acc[1].z += w0.y * av.z; acc[1].w += w0.y * av.w;
        acc[2].x += w0.z * av.x; acc[2].y += w0.z * av.y; acc[2].z += w0.z * av.z; acc[2].w += w0.z * av.w;
        acc[3].x += w0.w * av.x; acc[3].y += w0.w * av.y; acc[3].z += w0.w * av.z; acc[3].w += w0.w * av.w;
        acc[4].x += w1.x * av.x; acc[4].y += w1.x * av.y; acc[4].z += w1.x * av.z; acc[4].w += w1.x * av.w;
        acc[5].x += w1.y * av.x; acc[5].y += w1.y * av.y; acc[5].z += w1.y * av.z; acc[5].w += w1.y * av.w;
        acc[6].x += w1.z * av.x; acc[6].y += w1.z * av.y; acc[6].z += w1.z * av.z; acc[6].w += w1.z * av.w;
        acc[7].x += w1.w * av.x; acc[7].y += w1.w * av.y; acc[7].z += w1.w * av.z; acc[7].w += w1.w * av.w;
    }
    // conv channels (hin: read exactly once, streaming)
    const float* hp = hin + (size_t)(b * 64) * LQ + l;
#pragma unroll 4
    for (int c = 0; c < 64; c++) {
        float4 av = *(const float4*)(hp + (size_t)c * LQ);
        float4 w0 = *(const float4*)(wbase + (32 + c) * 64);
        float4 w1 = *(const float4*)(wbase + (32 + c) * 64 + 4);
        acc[0].x += w0.x * av.x; acc[0].y += w0.x * av.y; acc[0].z += w0.x * av.z; acc[0].w += w0.x * av.w;
        acc[1].x += w0.y * av.x; acc[1].y += w0.y * av.y; acc[1].z += w0.y * av.z; acc[1].w += w0.y * av.w;
        acc[2].x += w0.z * av.x; acc[2].y += w0.z * av.y; acc[2].z += w0.z * av.z; acc[2].w += w0.z * av.w;
        acc[3].x += w0.w * av.x; acc[3].y += w0.w * av.y; acc[3].z += w0.w * av.z; acc[3].w += w0.w * av.w;
        acc[4].x += w1.x * av.x; acc[4].y += w1.x * av.y; acc[4].z += w1.x * av.z; acc[4].w += w1.x * av.w;
        acc[5].x += w1.y * av.x; acc[5].y += w1.y * av.y; acc[5].z += w1.y * av.z; acc[5].w += w1.y * av.w;
        acc[6].x += w1.z * av.x; acc[6].y += w1.z * av.y; acc[6].z += w1.z * av.z; acc[6].w += w1.z * av.w;
        acc[7].x += w1.w * av.x; acc[7].y += w1.w * av.y; acc[7].z += w1.w * av.z; acc[7].w += w1.w * av.w;
    }

#pragma unroll
    for (int j = 0; j < 8; j++) {
        int o = og * 8 + j;
        float4 r = make_float4(gelu_exact(acc[j].x), gelu_exact(acc[j].y),
                               gelu_exact(acc[j].z), gelu_exact(acc[j].w));
        *(float4*)&hout[(size_t)(b * 64 + o) * LQ + l] = r;
    }
}

// ---------------------------------------------------------------------------
// Projection: out[b,0,l] = sum_c Qw[c]*h[b,c,l] + Qb
// ---------------------------------------------------------------------------
__global__ void proj_kernel(const float* __restrict__ h,
                            const float* __restrict__ Qw,
                            const float* __restrict__ Qb,
                            float* __restrict__ out) {
    int b = blockIdx.y;
    int l = blockIdx.x * 256 + threadIdx.x;
    float acc = Qb[0];
#pragma unroll
    for (int c = 0; c < 64; c++)
        acc += Qw[c] * h[(b * 64 + c) * LQ + l];
    out[b * LQ + l] = acc;
}

// ---------------------------------------------------------------------------
extern "C" void kernel_launch(void* const* d_in, const int* in_sizes, int n_in,
                              void* d_out, int out_size) {
    const float* x   = (const float*)d_in[0];
    const float* Pw  = (const float*)d_in[1];
    const float* Pb  = (const float*)d_in[2];
    const float* kwr = (const float*)d_in[3];
    const float* kwi = (const float*)d_in[4];
    const float* cw  = (const float*)d_in[5];
    const float* cb  = (const float*)d_in[6];
    const float* Qw  = (const float*)d_in[7];
    const float* Qb  = (const float*)d_in[8];
    float* out = (float*)d_out;

    float *hA = nullptr, *hB = nullptr;
    cudaGetSymbolAddress((void**)&hA, g_hA);
    cudaGetSymbolAddress((void**)&hB, g_hB);

    const int FWD_SMEM = (64 * 129 + 128 * 32) * 4;   // 49408 B
    cudaFuncSetAttribute(fwd_dft_kernel,
                         cudaFuncAttributeMaxDynamicSharedMemorySize, FWD_SMEM);

    build_table_kernel<<<(LQ * MQ) / 256, 256>>>();
    lift_kernel<<<(BQ * WQ * LQ) / 256, 256>>>(x, Pw, Pb, hA);

    float* cur = hA;
    float* nxt = hB;
    for (int ib = 0; ib < 4; ib++) {
        fwd_dft_kernel<<<dim3(BQ, KSPL), 128, FWD_SMEM>>>(cur);
        mode_mix_kernel<<<BQ * MQ, 64>>>(kwr, kwi, ib);
        fused_block_kernel<<<dim3(LQ / 128, BQ), 256>>>(cur, nxt, cw, cb, ib);
        float* tmp = cur; cur = nxt; nxt = tmp;
    }
    proj_kernel<<<dim3(LQ / 256, BQ), 256>>>(cur, Qw, Qb, out);
}

// round 4
// speedup vs baseline: 1.5364x; 1.0286x over previous
#include <cuda_runtime.h>
#include <math.h>

// Problem constants
#define BQ 32
#define DAQ 2
#define WQ 64
#define MQ 16
#define LQ 8192
#define NBQ 32          // 2*MODES (interleaved cos/sin channels)
#define KSPL 32         // K-split for forward DFT

// Scratch (device globals: allocation-free rule)
__device__ float g_hA[BQ * WQ * LQ];            // 64 MB
__device__ float g_hB[BQ * WQ * LQ];            // 64 MB
__device__ float g_T[LQ * NBQ];                 // basis [l][n]  (1 MB)
__device__ float g_Tt[NBQ * LQ];                // basis transposed [n][l] (1 MB)
__device__ float g_Fpart[BQ * KSPL * WQ * NBQ]; // forward DFT partials (8 MB)
__device__ float g_coef[BQ * WQ * NBQ];         // inverse-DFT coefficients (1 MB)

__device__ __forceinline__ float gelu_exact(float v) {
    return 0.5f * v * (1.0f + erff(v * 0.70710678118654752440f));
}

// ---------------------------------------------------------------------------
// Basis tables. T[l][2k]=cos(2pi k l/L), T[l][2k+1]=sin(...); Tt = transpose.
// ---------------------------------------------------------------------------
__global__ void build_table_kernel() {
    int idx = blockIdx.x * blockDim.x + threadIdx.x;  // 131072
    int k = idx >> 13;
    int l = idx & (LQ - 1);
    int m = (k * l) & (LQ - 1);
    float ang = (float)m * (6.283185307179586476925f / (float)LQ);
    float s, c;
    sincosf(ang, &s, &c);
    g_T[l * NBQ + 2 * k]     = c;
    g_T[l * NBQ + 2 * k + 1] = s;
    g_Tt[(2 * k) * LQ + l]     = c;
    g_Tt[(2 * k + 1) * LQ + l] = s;
}

// ---------------------------------------------------------------------------
// Lifting: h[b,w,l] = Pw[w,0]*x[b,0,l] + Pw[w,1]*x[b,1,l] + Pb[w]
// ---------------------------------------------------------------------------
__global__ void lift_kernel(const float* __restrict__ x,
                            const float* __restrict__ Pw,
                            const float* __restrict__ Pb,
                            float* __restrict__ h) {
    int idx = blockIdx.x * 256 + threadIdx.x;
    int l = idx & (LQ - 1);
    int w = (idx >> 13) & 63;
    int b = idx >> 19;
    float x0 = x[(b * 2 + 0) * LQ + l];
    float x1 = x[(b * 2 + 1) * LQ + l];
    h[idx] = Pw[2 * w] * x0 + Pw[2 * w + 1] * x1 + Pb[w];
}

// ---------------------------------------------------------------------------
// Forward DFT (16 modes) tiled GEMM.
//   Fpart[b, ks, c, n] = sum over 256-l slice of h[b,c,l] * T[l,n]
// Grid (B, KSPL=32); 128 threads; 25KB static smem (64-l chunks) ->
// ~8 CTA/SM possible, 1024 CTAs -> ~44% occupancy.
// Thread: cc=t&31 owns c in {cc, cc+32}; nq=(t>>5)*8 owns 8 n's. 16 acc.
// ---------------------------------------------------------------------------
__global__ void __launch_bounds__(128) fwd_dft_kernel(const float* __restrict__ h) {
    __shared__ float Ht[64 * 65];
    __shared__ __align__(16) float Tt[64 * 32];
    int b = blockIdx.x;
    int ks = blockIdx.y;
    int t = threadIdx.x;
    int cc = t & 31;
    int nq = (t >> 5) << 3;        // 0,8,16,24
    float acc0[8] = {0.f, 0.f, 0.f, 0.f, 0.f, 0.f, 0.f, 0.f};
    float acc1[8] = {0.f, 0.f, 0.f, 0.f, 0.f, 0.f, 0.f, 0.f};
    const int lbase = ks * (LQ / KSPL);  // 256

    for (int chk = 0; chk < 4; chk++) {
        int l0 = lbase + chk * 64;
        __syncthreads();
#pragma unroll
        for (int j = 0; j < 32; j++) {
            int idx = t + 128 * j;       // 4096 floats
            int c = idx >> 6, l = idx & 63;
            Ht[c * 65 + l] = h[(b * 64 + c) * LQ + l0 + l];
        }
#pragma unroll
        for (int j = 0; j < 4; j++) {
            int idx = t + 128 * j;       // 512 float4 = 64x32 floats
            ((float4*)Tt)[idx] = ((const float4*)g_T)[l0 * 8 + idx];
        }
        __syncthreads();
#pragma unroll 4
        for (int l = 0; l < 64; l++) {
            float a0 = Ht[cc * 65 + l];
            float a1 = Ht[(cc + 32) * 65 + l];
            float4 bv0 = *(float4*)(Tt + l * 32 + nq);       // broadcast
            float4 bv1 = *(float4*)(Tt + l * 32 + nq + 4);   // broadcast
            acc0[0] += a0 * bv0.x; acc0[1] += a0 * bv0.y;
            acc0[2] += a0 * bv0.z; acc0[3] += a0 * bv0.w;
            acc0[4] += a0 * bv1.x; acc0[5] += a0 * bv1.y;
            acc0[6] += a0 * bv1.z; acc0[7] += a0 * bv1.w;
            acc1[0] += a1 * bv0.x; acc1[1] += a1 * bv0.y;
            acc1[2] += a1 * bv0.z; acc1[3] += a1 * bv0.w;
            acc1[4] += a1 * bv1.x; acc1[5] += a1 * bv1.y;
            acc1[6] += a1 * bv1.z; acc1[7] += a1 * bv1.w;
        }
    }
    int base0 = ((b * KSPL + ks) * 64 + cc) * NBQ + nq;
    int base1 = ((b * KSPL + ks) * 64 + cc + 32) * NBQ + nq;
    *(float4*)(g_Fpart + base0)     = make_float4(acc0[0], acc0[1], acc0[2], acc0[3]);
    *(float4*)(g_Fpart + base0 + 4) = make_float4(acc0[4], acc0[5], acc0[6], acc0[7]);
    *(float4*)(g_Fpart + base1)     = make_float4(acc1[0], acc1[1], acc1[2], acc1[3]);
    *(float4*)(g_Fpart + base1 + 4) = make_float4(acc1[4], acc1[5], acc1[6], acc1[7]);
}

// ---------------------------------------------------------------------------
// Mode mixing + irfft coefficient prep.
// Grid (k=16, bg=8); 256 threads = 4 b-lanes x 64 o. Weights staged once
// per CTA (amortized over 4 batches), padded stride 65 -> conflict-free.
// ---------------------------------------------------------------------------
__global__ void __launch_bounds__(256) mode_mix_kernel(const float* __restrict__ kwr,
                                                       const float* __restrict__ kwi, int ib) {
    int k = blockIdx.x;
    int bg = blockIdx.y;
    int t = threadIdx.x;
    int o = t & 63;
    int bb = t >> 6;
    int b = bg * 4 + bb;
    __shared__ float wrS[64 * 65], wiS[64 * 65];
    __shared__ float HrS[4][64], HsS[4][64];

    const float* wrG = kwr + ((size_t)ib * 16 + k) * 4096;
    const float* wiG = kwi + ((size_t)ib * 16 + k) * 4096;
#pragma unroll
    for (int j = 0; j < 16; j++) {
        int idx = t + 256 * j;          // 4096
        int row = idx >> 6, col = idx & 63;
        wrS[row * 65 + col] = wrG[idx];
        wiS[row * 65 + col] = wiG[idx];
    }

    float hr = 0.f, hs = 0.f;
#pragma unroll
    for (int p = 0; p < KSPL; p++) {
        hr += g_Fpart[((b * KSPL + p) * 64 + o) * NBQ + 2 * k];
        hs += g_Fpart[((b * KSPL + p) * 64 + o) * NBQ + 2 * k + 1];
    }
    HrS[bb][o] = hr;
    HsS[bb][o] = hs;
    __syncthreads();

    float ar = 0.f, ai = 0.f;
#pragma unroll 8
    for (int i = 0; i < 64; i++) {
        float xr = HrS[bb][i];
        float xi = -HsS[bb][i];
        float wrv = wrS[o * 65 + i];
        float wiv = wiS[o * 65 + i];
        ar += wrv * xr - wiv * xi;
        ai += wrv * xi + wiv * xr;
    }
    const float invL = 1.0f / (float)LQ;
    float cC, cS;
    if (k == 0) { cC = ar * invL;        cS = 0.f; }
    else        { cC = 2.f * ar * invL;  cS = -2.f * ai * invL; }
    g_coef[(b * 64 + o) * NBQ + 2 * k]     = cC;
    g_coef[(b * 64 + o) * NBQ + 2 * k + 1] = cS;
}

// ---------------------------------------------------------------------------
// Fused inverse-DFT + 1x1 conv + bias + exact GELU (register-tiled GEMM):
//   C[o=64, l-tile=128] = W[96,64]^T * A[96, l-tile]
// A rows 0..31 = basis (g_Tt), rows 32..95 = hin channels.
// 256 threads: og=t>>5 owns 8 o's, lg=t&31 owns l-quad. Per k-step:
// 1 coalesced LDG.128 + 2 broadcast LDS.128 -> 32 FFMA.
// LAST=true additionally fuses the output projection (out = Qw . gelu + Qb)
// and skips the hout store entirely.
// ---------------------------------------------------------------------------
template <bool LAST>
__global__ void __launch_bounds__(256) fused_block_kernel(
    const float* __restrict__ hin, float* __restrict__ hout,
    const float* __restrict__ cw, const float* __restrict__ cb, int ib,
    const float* __restrict__ Qw, const float* __restrict__ Qb,
    float* __restrict__ outp) {
    __shared__ __align__(16) float wS[96 * 64];   // [ch][o]: 32 coef + 64 conv
    __shared__ float biasS[64];
    __shared__ float partS[8][128];               // only used when LAST
    int b = blockIdx.y;
    int t = threadIdx.x;
    int og = t >> 5;                 // 0..7
    int lg = t & 31;
    int l0 = blockIdx.x * 128;
    int l = l0 + lg * 4;

#pragma unroll
    for (int j = 0; j < 8; j++) {           // 2048 coef
        int idx = t + 256 * j;
        int o = idx >> 5, n = idx & 31;
        wS[n * 64 + o] = g_coef[(b * 64 + o) * NBQ + n];
    }
#pragma unroll
    for (int j = 0; j < 16; j++) {          // 4096 conv
        int idx = t + 256 * j;
        int o = idx >> 6, c = idx & 63;
        wS[(32 + c) * 64 + o] = cw[((size_t)ib * 64 + o) * 64 + c];
    }
    if (t < 64) biasS[t] = cb[ib * 64 + t];
    __syncthreads();

    float4 acc[8];
#pragma unroll
    for (int j = 0; j < 8; j++) {
        float bv = biasS[og * 8 + j];
        acc[j] = make_float4(bv, bv, bv, bv);
    }

    const float* wbase = wS + og * 8;

    // basis channels (g_Tt: L2-resident, shared across all b)
    const float* tp = g_Tt + l;
#pragma unroll 4
    for (int ch = 0; ch < 32; ch++) {
        float4 av = *(const float4*)(tp + (size_t)ch * LQ);
        float4 w0 = *(const float4*)(wbase + ch * 64);       // broadcast
        float4 w1 = *(const float4*)(wbase + ch * 64 + 4);   // broadcast
        acc[0].x += w0.x * av.x; acc[0].y += w0.x * av.y; acc[0].z += w0.x * av.z; acc[0].w += w0.x * av.w;
        acc[1].x += w0.y * av.x; acc[1].y += w0.y * av.y; acc[1].z += w0.y * av.z; acc[1].w += w0.y * av.w;
        acc[2].x += w0.z * av.x; acc[2].y += w0.z * av.y; acc[2].z += w0.z * av.z; acc[2].w += w0.z * av.w;
        acc[3].x += w0.w * av.x; acc[3].y += w0.w * av.y; acc[3].z += w0.w * av.z; acc[3].w += w0.w * av.w;
        acc[4].x += w1.x * av.x; acc[4].y += w1.x * av.y; acc[4].z += w1.x * av.z; acc[4].w += w1.x * av.w;
        acc[5].x += w1.y * av.x; acc[5].y += w1.y * av.y; acc[5].z += w1.y * av.z; acc[5].w += w1.y * av.w;
        acc[6].x += w1.z * av.x; acc[6].y += w1.z * av.y; acc[6].z += w1.z * av.z; acc[6].w += w1.z * av.w;
        acc[7].x += w1.w * av.x; acc[7].y += w1.w * av.y; acc[7].z += w1.w * av.z; acc[7].w += w1.w * av.w;
    }
    // conv channels (hin: read exactly once, streaming)
    const float* hp = hin + (size_t)(b * 64) * LQ + l;
#pragma unroll 4
    for (int c = 0; c < 64; c++) {
        float4 av = *(const float4*)(hp + (size_t)c * LQ);
        float4 w0 = *(const float4*)(wbase + (32 + c) * 64);
        float4 w1 = *(const float4*)(wbase + (32 + c) * 64 + 4);
        acc[0].x += w0.x * av.x; acc[0].y += w0.x * av.y; acc[0].z += w0.x * av.z; acc[0].w += w0.x * av.w;
        acc[1].x += w0.y * av.x; acc[1].y += w0.y * av.y; acc[1].z += w0.y * av.z; acc[1].w += w0.y * av.w;
        acc[2].x += w0.z * av.x; acc[2].y += w0.z * av.y; acc[2].z += w0.z * av.z; acc[2].w += w0.z * av.w;
        acc[3].x += w0.w * av.x; acc[3].y += w0.w * av.y; acc[3].z += w0.w * av.z; acc[3].w += w0.w * av.w;
        acc[4].x += w1.x * av.x; acc[4].y += w1.x * av.y; acc[4].z += w1.x * av.z; acc[4].w += w1.x * av.w;
        acc[5].x += w1.y * av.x; acc[5].y += w1.y * av.y; acc[5].z += w1.y * av.z; acc[5].w += w1.y * av.w;
        acc[6].x += w1.z * av.x; acc[6].y += w1.z * av.y; acc[6].z += w1.z * av.z; acc[6].w += w1.z * av.w;
        acc[7].x += w1.w * av.x; acc[7].y += w1.w * av.y; acc[7].z += w1.w * av.z; acc[7].w += w1.w * av.w;
    }

    if (!LAST) {
#pragma unroll
        for (int j = 0; j < 8; j++) {
            int o = og * 8 + j;
            float4 r = make_float4(gelu_exact(acc[j].x), gelu_exact(acc[j].y),
                                   gelu_exact(acc[j].z), gelu_exact(acc[j].w));
            *(float4*)&hout[(size_t)(b * 64 + o) * LQ + l] = r;
        }
    } else {
        // fused projection: out[b, l] = Qb + sum_o Qw[o] * gelu(...)
        float4 ps = make_float4(0.f, 0.f, 0.f, 0.f);
#pragma unroll
        for (int j = 0; j < 8; j++) {
            float qv = __ldg(&Qw[og * 8 + j]);
            ps.x += qv * gelu_exact(acc[j].x);
            ps.y += qv * gelu_exact(acc[j].y);
            ps.z += qv * gelu_exact(acc[j].z);
            ps.w += qv * gelu_exact(acc[j].w);
        }
        *(float4*)&partS[og][lg * 4] = ps;
        __syncthreads();
        if (t < 128) {
            float s = __ldg(&Qb[0]);
#pragma unroll
            for (int g = 0; g < 8; g++) s += partS[g][t];
            outp[(size_t)b * LQ + l0 + t] = s;
        }
    }
}

// ---------------------------------------------------------------------------
extern "C" void kernel_launch(void* const* d_in, const int* in_sizes, int n_in,
                              void* d_out, int out_size) {
    const float* x   = (const float*)d_in[0];
    const float* Pw  = (const float*)d_in[1];
    const float* Pb  = (const float*)d_in[2];
    const float* kwr = (const float*)d_in[3];
    const float* kwi = (const float*)d_in[4];
    const float* cw  = (const float*)d_in[5];
    const float* cb  = (const float*)d_in[6];
    const float* Qw  = (const float*)d_in[7];
    const float* Qb  = (const float*)d_in[8];
    float* out = (float*)d_out;

    float *hA = nullptr, *hB = nullptr;
    cudaGetSymbolAddress((void**)&hA, g_hA);
    cudaGetSymbolAddress((void**)&hB, g_hB);

    build_table_kernel<<<(LQ * MQ) / 256, 256>>>();
    lift_kernel<<<(BQ * WQ * LQ) / 256, 256>>>(x, Pw, Pb, hA);

    float* cur = hA;
    float* nxt = hB;
    for (int ib = 0; ib < 4; ib++) {
        fwd_dft_kernel<<<dim3(BQ, KSPL), 128>>>(cur);
        mode_mix_kernel<<<dim3(16, 8), 256>>>(kwr, kwi, ib);
        if (ib < 3) {
            fused_block_kernel<false><<<dim3(LQ / 128, BQ), 256>>>(
                cur, nxt, cw, cb, ib, Qw, Qb, out);
        } else {
            fused_block_kernel<true><<<dim3(LQ / 128, BQ), 256>>>(
                cur, nxt, cw, cb, ib, Qw, Qb, out);
        }
        float* tmp = cur; cur = nxt; nxt = tmp;
    }
}

// round 5
// speedup vs baseline: 1.7520x; 1.1403x over previous
#include <cuda_runtime.h>
#include <math.h>

// Problem constants
#define BQ 32
#define DAQ 2
#define WQ 64
#define MQ 16
#define LQ 8192
#define LH 4096         // L/2 (half-period folding)
#define NBQ 32          // 2*MODES (interleaved cos/sin channels)
#define KSPL 16         // K-split over the folded half-range

// Scratch (device globals: allocation-free rule)
__device__ float g_hA[BQ * WQ * LQ];            // 64 MB
__device__ float g_hB[BQ * WQ * LQ];            // 64 MB
__device__ float g_T[LQ * NBQ];                 // basis [l][n]  (1 MB)
__device__ float g_Tt[NBQ * LQ];                // basis transposed [n][l] (1 MB)
__device__ float g_Fpart[BQ * NBQ * KSPL * WQ]; // DFT partials, [b][n][p][c] (4 MB)
__device__ float g_coef[BQ * WQ * NBQ];         // inverse-DFT coefficients (1 MB)

__device__ __forceinline__ float gelu_exact(float v) {
    return 0.5f * v * (1.0f + erff(v * 0.70710678118654752440f));
}

// ---------------------------------------------------------------------------
// Basis tables. T[l][2k]=cos(2pi k l/L), T[l][2k+1]=sin(...); Tt = transpose.
// ---------------------------------------------------------------------------
__global__ void build_table_kernel() {
    int idx = blockIdx.x * blockDim.x + threadIdx.x;  // 131072
    int k = idx >> 13;
    int l = idx & (LQ - 1);
    int m = (k * l) & (LQ - 1);
    float ang = (float)m * (6.283185307179586476925f / (float)LQ);
    float s, c;
    sincosf(ang, &s, &c);
    g_T[l * NBQ + 2 * k]     = c;
    g_T[l * NBQ + 2 * k + 1] = s;
    g_Tt[(2 * k) * LQ + l]     = c;
    g_Tt[(2 * k + 1) * LQ + l] = s;
}

// ---------------------------------------------------------------------------
// Lifting: h[b,w,l] = Pw[w,0]*x[b,0,l] + Pw[w,1]*x[b,1,l] + Pb[w]
// ---------------------------------------------------------------------------
__global__ void lift_kernel(const float* __restrict__ x,
                            const float* __restrict__ Pw,
                            const float* __restrict__ Pb,
                            float* __restrict__ h) {
    int idx = blockIdx.x * 256 + threadIdx.x;
    int l = idx & (LQ - 1);
    int w = (idx >> 13) & 63;
    int b = idx >> 19;
    float x0 = x[(b * 2 + 0) * LQ + l];
    float x1 = x[(b * 2 + 1) * LQ + l];
    h[idx] = Pw[2 * w] * x0 + Pw[2 * w + 1] * x1 + Pb[w];
}

// ---------------------------------------------------------------------------
// Forward DFT (16 modes) with half-period folding:
//   e[l] = h[l] + h[l+L/2], o[l] = h[l] - h[l+L/2]  (l < L/2)
//   F_k  = sum_{l<L/2} (k even ? e : o)[l] * trig_k(l)
// Grid (B, KSPL=16); 128 threads. Thread: cc=t&31 owns c in {cc,cc+32};
// nq=(t>>5)*8 owns n in [nq,nq+8) -> k parities E,E,O,O,E,E,O,O.
// Output layout g_Fpart[b][n][p][c]: coalesced STG (lane=cc) and coalesced
// gather in mode_mix (lane=c).
// ---------------------------------------------------------------------------
__global__ void __launch_bounds__(128) fwd_dft_kernel(const float* __restrict__ h) {
    __shared__ float Es[64 * 65];
    __shared__ float Os[64 * 65];
    __shared__ __align__(16) float Tt[64 * 32];
    int b = blockIdx.x;
    int ks = blockIdx.y;
    int t = threadIdx.x;
    int cc = t & 31;
    int nq = (t >> 5) << 3;        // 0,8,16,24
    float acc0[8] = {0.f, 0.f, 0.f, 0.f, 0.f, 0.f, 0.f, 0.f};
    float acc1[8] = {0.f, 0.f, 0.f, 0.f, 0.f, 0.f, 0.f, 0.f};
    const int lbase = ks * (LH / KSPL);  // 256-wide slice of [0, 4096)

    for (int chk = 0; chk < 4; chk++) {
        int l0 = lbase + chk * 64;
        __syncthreads();
#pragma unroll
        for (int j = 0; j < 32; j++) {
            int idx = t + 128 * j;       // 4096 elements
            int c = idx >> 6, l = idx & 63;
            const float* hp = h + (size_t)(b * 64 + c) * LQ + l0 + l;
            float v1 = hp[0];
            float v2 = hp[LH];
            Es[c * 65 + l] = v1 + v2;
            Os[c * 65 + l] = v1 - v2;
        }
#pragma unroll
        for (int j = 0; j < 4; j++) {
            int idx = t + 128 * j;       // 512 float4 = 64x32 floats
            ((float4*)Tt)[idx] = ((const float4*)g_T)[l0 * 8 + idx];
        }
        __syncthreads();
#pragma unroll 4
        for (int l = 0; l < 64; l++) {
            float e0 = Es[cc * 65 + l];
            float e1 = Es[(cc + 32) * 65 + l];
            float o0 = Os[cc * 65 + l];
            float o1 = Os[(cc + 32) * 65 + l];
            float4 bv0 = *(float4*)(Tt + l * 32 + nq);       // broadcast
            float4 bv1 = *(float4*)(Tt + l * 32 + nq + 4);   // broadcast
            // j=0,1 (k even)->e ; j=2,3 (k odd)->o ; j=4,5->e ; j=6,7->o
            acc0[0] += e0 * bv0.x; acc0[1] += e0 * bv0.y;
            acc0[2] += o0 * bv0.z; acc0[3] += o0 * bv0.w;
            acc0[4] += e0 * bv1.x; acc0[5] += e0 * bv1.y;
            acc0[6] += o0 * bv1.z; acc0[7] += o0 * bv1.w;
            acc1[0] += e1 * bv0.x; acc1[1] += e1 * bv0.y;
            acc1[2] += o1 * bv0.z; acc1[3] += o1 * bv0.w;
            acc1[4] += e1 * bv1.x; acc1[5] += e1 * bv1.y;
            acc1[6] += o1 * bv1.z; acc1[7] += o1 * bv1.w;
        }
    }
#pragma unroll
    for (int j = 0; j < 8; j++) {
        int n = nq + j;
        size_t base = ((size_t)(b * NBQ + n) * KSPL + ks) * 64;
        g_Fpart[base + cc]      = acc0[j];   // coalesced: lane = cc
        g_Fpart[base + cc + 32] = acc1[j];
    }
}

// ---------------------------------------------------------------------------
// Mode mixing + irfft coefficient prep.
// Grid (k=16, bg=8); 256 threads = 4 b-lanes x 64 o. Weights staged once
// per CTA (amortized over 4 batches), padded stride 65 -> conflict-free.
// Fpart gather is fully coalesced (lane = c).
// ---------------------------------------------------------------------------
__global__ void __launch_bounds__(256) mode_mix_kernel(const float* __restrict__ kwr,
                                                       const float* __restrict__ kwi, int ib) {
    int k = blockIdx.x;
    int bg = blockIdx.y;
    int t = threadIdx.x;
    int o = t & 63;
    int bb = t >> 6;
    int b = bg * 4 + bb;
    __shared__ float wrS[64 * 65], wiS[64 * 65];
    __shared__ float HrS[4][64], HsS[4][64];

    const float* wrG = kwr + ((size_t)ib * 16 + k) * 4096;
    const float* wiG = kwi + ((size_t)ib * 16 + k) * 4096;
#pragma unroll
    for (int j = 0; j < 16; j++) {
        int idx = t + 256 * j;          // 4096
        int row = idx >> 6, col = idx & 63;
        wrS[row * 65 + col] = wrG[idx];
        wiS[row * 65 + col] = wiG[idx];
    }

    float hr = 0.f, hs = 0.f;
    const float* fr = g_Fpart + (size_t)(b * NBQ + 2 * k) * KSPL * 64;
    const float* fs = g_Fpart + (size_t)(b * NBQ + 2 * k + 1) * KSPL * 64;
#pragma unroll
    for (int p = 0; p < KSPL; p++) {
        hr += fr[p * 64 + o];           // coalesced
        hs += fs[p * 64 + o];
    }
    HrS[bb][o] = hr;
    HsS[bb][o] = hs;
    __syncthreads();

    float ar = 0.f, ai = 0.f;
#pragma unroll 8
    for (int i = 0; i < 64; i++) {
        float xr = HrS[bb][i];
        float xi = -HsS[bb][i];
        float wrv = wrS[o * 65 + i];
        float wiv = wiS[o * 65 + i];
        ar += wrv * xr - wiv * xi;
        ai += wrv * xi + wiv * xr;
    }
    const float invL = 1.0f / (float)LQ;
    float cC, cS;
    if (k == 0) { cC = ar * invL;        cS = 0.f; }
    else        { cC = 2.f * ar * invL;  cS = -2.f * ai * invL; }
    g_coef[(b * 64 + o) * NBQ + 2 * k]     = cC;
    g_coef[(b * 64 + o) * NBQ + 2 * k + 1] = cS;
}

// ---------------------------------------------------------------------------
// Fused inverse-DFT + 1x1 conv + bias + exact GELU (register-tiled GEMM):
//   C[o=64, l-tile=128] = W[96,64]^T * A[96, l-tile]
// A rows 0..31 = basis (g_Tt), rows 32..95 = hin channels.
// 256 threads: og=t>>5 owns 8 o's, lg=t&31 owns l-quad. Per k-step:
// 1 coalesced LDG.128 + 2 broadcast LDS.128 -> 32 FFMA.
// LAST=true fuses the output projection and skips the hout store.
// ---------------------------------------------------------------------------
template <bool LAST>
__global__ void __launch_bounds__(256) fused_block_kernel(
    const float* __restrict__ hin, float* __restrict__ hout,
    const float* __restrict__ cw, const float* __restrict__ cb, int ib,
    const float* __restrict__ Qw, const float* __restrict__ Qb,
    float* __restrict__ outp) {
    __shared__ __align__(16) float wS[96 * 64];   // [ch][o]: 32 coef + 64 conv
    __shared__ float biasS[64];
    __shared__ float partS[8][128];               // only used when LAST
    int b = blockIdx.y;
    int t = threadIdx.x;
    int og = t >> 5;                 // 0..7
    int lg = t & 31;
    int l0 = blockIdx.x * 128;
    int l = l0 + lg * 4;

#pragma unroll
    for (int j = 0; j < 8; j++) {           // 2048 coef
        int idx = t + 256 * j;
        int o = idx >> 5, n = idx & 31;
        wS[n * 64 + o] = g_coef[(b * 64 + o) * NBQ + n];
    }
#pragma unroll
    for (int j = 0; j < 16; j++) {          // 4096 conv
        int idx = t + 256 * j;
        int o = idx >> 6, c = idx & 63;
        wS[(32 + c) * 64 + o] = cw[((size_t)ib * 64 + o) * 64 + c];
    }
    if (t < 64) biasS[t] = cb[ib * 64 + t];
    __syncthreads();

    float4 acc[8];
#pragma unroll
    for (int j = 0; j < 8; j++) {
        float bv = biasS[og * 8 + j];
        acc[j] = make_float4(bv, bv, bv, bv);
    }

    const float* wbase = wS + og * 8;

    // basis channels (g_Tt: L2-resident, shared across all b)
    const float* tp = g_Tt + l;
#pragma unroll 4
    for (int ch = 0; ch < 32; ch++) {
        float4 av = *(const float4*)(tp + (size_t)ch * LQ);
        float4 w0 = *(const float4*)(wbase + ch * 64);       // broadcast
        float4 w1 = *(const float4*)(wbase + ch * 64 + 4);   // broadcast
        acc[0].x += w0.x * av.x; acc[0].y += w0.x * av.y; acc[0].z += w0.x * av.z; acc[0].w += w0.x * av.w;
        acc[1].x += w0.y * av.x; acc[1].y += w0.y * av.y; acc[1].z += w0.y * av.z; acc[1].w += w0.y * av.w;
        acc[2].x += w0.z * av.x; acc[2].y += w0.z * av.y; acc[2].z += w0.z * av.z; acc[2].w += w0.z * av.w;
        acc[3].x += w0.w * av.x; acc[3].y += w0.w * av.y; acc[3].z += w0.w * av.z; acc[3].w += w0.w * av.w;
        acc[4].x += w1.x * av.x; acc[4].y += w1.x * av.y; acc[4].z += w1.x * av.z; acc[4].w += w1.x * av.w;
        acc[5].x += w1.y * av.x; acc[5].y += w1.y * av.y; acc[5].z += w1.y * av.z; acc[5].w += w1.y * av.w;
        acc[6].x += w1.z * av.x; acc[6].y += w1.z * av.y; acc[6].z += w1.z * av.z; acc[6].w += w1.z * av.w;
        acc[7].x += w1.w * av.x; acc[7].y += w1.w * av.y; acc[7].z += w1.w * av.z; acc[7].w += w1.w * av.w;
    }
    // conv channels (hin: read exactly once, streaming)
    const float* hp = hin + (size_t)(b * 64) * LQ + l;
#pragma unroll 4
    for (int c = 0; c < 64; c++) {
        float4 av = *(const float4*)(hp + (size_t)c * LQ);
        float4 w0 = *(const float4*)(wbase + (32 + c) * 64);
        float4 w1 = *(const float4*)(wbase + (32 + c) * 64 + 4);
        acc[0].x += w0.x * av.x; acc[0].y += w0.x * av.y; acc[0].z += w0.x * av.z; acc[0].w += w0.x * av.w;
        acc[1].x += w0.y * av.x; acc[1].y += w0.y * av.y; acc[1].z += w0.y * av.z; acc[1].w += w0.y * av.w;
        acc[2].x += w0.z * av.x; acc[2].y += w0.z * av.y; acc[2].z += w0.z * av.z; acc[2].w += w0.z * av.w;
        acc[3].x += w0.w * av.x; acc[3].y += w0.w * av.y; acc[3].z += w0.w * av.z; acc[3].w += w0.w * av.w;
        acc[4].x += w1.x * av.x; acc[4].y += w1.x * av.y; acc[4].z += w1.x * av.z; acc[4].w += w1.x * av.w;
        acc[5].x += w1.y * av.x; acc[5].y += w1.y * av.y; acc[5].z += w1.y * av.z; acc[5].w += w1.y * av.w;
        acc[6].x += w1.z * av.x; acc[6].y += w1.z * av.y; acc[6].z += w1.z * av.z; acc[6].w += w1.z * av.w;
        acc[7].x += w1.w * av.x; acc[7].y += w1.w * av.y; acc[7].z += w1.w * av.z; acc[7].w += w1.w * av.w;
    }

    if (!LAST) {
#pragma unroll
        for (int j = 0; j < 8; j++) {
            int o = og * 8 + j;
            float4 r = make_float4(gelu_exact(acc[j].x), gelu_exact(acc[j].y),
                                   gelu_exact(acc[j].z), gelu_exact(acc[j].w));
            *(float4*)&hout[(size_t)(b * 64 + o) * LQ + l] = r;
        }
    } else {
        // fused projection: out[b, l] = Qb + sum_o Qw[o] * gelu(...)
        float4 ps = make_float4(0.f, 0.f, 0.f, 0.f);
#pragma unroll
        for (int j = 0; j < 8; j++) {
            float qv = __ldg(&Qw[og * 8 + j]);
            ps.x += qv * gelu_exact(acc[j].x);
            ps.y += qv * gelu_exact(acc[j].y);
            ps.z += qv * gelu_exact(acc[j].z);
            ps.w += qv * gelu_exact(acc[j].w);
        }
        *(float4*)&partS[og][lg * 4] = ps;
        __syncthreads();
        if (t < 128) {
            float s = __ldg(&Qb[0]);
#pragma unroll
            for (int g = 0; g < 8; g++) s += partS[g][t];
            outp[(size_t)b * LQ + l0 + t] = s;
        }
    }
}

// ---------------------------------------------------------------------------
extern "C" void kernel_launch(void* const* d_in, const int* in_sizes, int n_in,
                              void* d_out, int out_size) {
    const float* x   = (const float*)d_in[0];
    const float* Pw  = (const float*)d_in[1];
    const float* Pb  = (const float*)d_in[2];
    const float* kwr = (const float*)d_in[3];
    const float* kwi = (const float*)d_in[4];
    const float* cw  = (const float*)d_in[5];
    const float* cb  = (const float*)d_in[6];
    const float* Qw  = (const float*)d_in[7];
    const float* Qb  = (const float*)d_in[8];
    float* out = (float*)d_out;

    float *hA = nullptr, *hB = nullptr;
    cudaGetSymbolAddress((void**)&hA, g_hA);
    cudaGetSymbolAddress((void**)&hB, g_hB);

    build_table_kernel<<<(LQ * MQ) / 256, 256>>>();
    lift_kernel<<<(BQ * WQ * LQ) / 256, 256>>>(x, Pw, Pb, hA);

    float* cur = hA;
    float* nxt = hB;
    for (int ib = 0; ib < 4; ib++) {
        fwd_dft_kernel<<<dim3(BQ, KSPL), 128>>>(cur);
        mode_mix_kernel<<<dim3(16, 8), 256>>>(kwr, kwi, ib);
        if (ib < 3) {
            fused_block_kernel<false><<<dim3(LQ / 128, BQ), 256>>>(
                cur, nxt, cw, cb, ib, Qw, Qb, out);
        } else {
            fused_block_kernel<true><<<dim3(LQ / 128, BQ), 256>>>(
                cur, nxt, cw, cb, ib, Qw, Qb, out);
        }
        float* tmp = cur; cur = nxt; nxt = tmp;
    }
}

// round 7
// speedup vs baseline: 2.2538x; 1.2864x over previous
#include <cuda_runtime.h>
#include <cuda_bf16.h>
#include <math.h>
#include <stdint.h>

// Problem constants
#define BQ 32
#define WQ 64
#define MQ 16
#define LQ 8192
#define LH 4096
#define NBQ 32
#define KSPL 16

// ---------------- scratch (device globals: allocation-free rule) ----------
__device__ __align__(16) uint32_t g_hpkA[BQ * WQ * LQ];   // packed bf16 hi|lo h (64 MB)
__device__ __align__(16) uint32_t g_hpkB[BQ * WQ * LQ];   // 64 MB
__device__ float    g_T[LQ * NBQ];                        // fp32 basis [l][n] (1 MB)
__device__ __align__(16) uint32_t g_Tpk[NBQ * LQ];        // packed basis [n][l] (1 MB)
__device__ float    g_Fpart[BQ * NBQ * KSPL * WQ];        // DFT partials [b][n][p][c] (4 MB)
__device__ uint32_t g_coefpk[BQ * WQ * NBQ];              // packed coef (1 MB)
__device__ uint32_t g_convpk[4 * WQ * WQ];                // packed conv weights

__device__ __forceinline__ float gelu_exact(float v) {
    return 0.5f * v * (1.0f + erff(v * 0.70710678118654752440f));
}

// bf16 hi/lo packing: low 16 bits = hi part, high 16 bits = lo part
__device__ __forceinline__ uint32_t pk(float v) {
    __nv_bfloat16 h = __float2bfloat16(v);
    __nv_bfloat16 l = __float2bfloat16(v - __bfloat162float(h));
    return (uint32_t)__bfloat16_as_ushort(h) | ((uint32_t)__bfloat16_as_ushort(l) << 16);
}
__device__ __forceinline__ float upk(uint32_t u) {
    return __bfloat162float(__ushort_as_bfloat16((unsigned short)(u & 0xFFFFu)))
         + __bfloat162float(__ushort_as_bfloat16((unsigned short)(u >> 16)));
}

// warp-level bf16 MMA (baseline PTX, sm_80+; runs on tensor pipe)
__device__ __forceinline__ void mma16816(float* d, const uint32_t* a,
                                         uint32_t b0, uint32_t b1) {
    asm volatile(
        "mma.sync.aligned.m16n8k16.row.col.f32.bf16.bf16.f32 "
        "{%0,%1,%2,%3}, {%4,%5,%6,%7}, {%8,%9}, {%0,%1,%2,%3};"
        : "+f"(d[0]), "+f"(d[1]), "+f"(d[2]), "+f"(d[3])
        : "r"(a[0]), "r"(a[1]), "r"(a[2]), "r"(a[3]), "r"(b0), "r"(b1));
}

// smem layout for fused kernel (bytes)
#define AS_B 404                       // A/B row stride: 202 bf16
#define OFF_A   0                      // A: 128 x 404 = 51712 (reused as D fp32 64x129)
#define OFF_BHI 51712                  // B_hi: 64 x 404 = 25856
#define OFF_BLO 77568                  // B_lo: 64 x 404 = 25856
#define FUSED_SMEM 103424

// ---------------------------------------------------------------------------
// Basis tables
// ---------------------------------------------------------------------------
__global__ void build_table_kernel() {
    int idx = blockIdx.x * blockDim.x + threadIdx.x;  // 131072
    int k = idx >> 13;
    int l = idx & (LQ - 1);
    int m = (k * l) & (LQ - 1);
    float ang = (float)m * (6.283185307179586476925f / (float)LQ);
    float s, c;
    sincosf(ang, &s, &c);
    g_T[l * NBQ + 2 * k]     = c;
    g_T[l * NBQ + 2 * k + 1] = s;
    g_Tpk[(2 * k) * LQ + l]     = pk(c);
    g_Tpk[(2 * k + 1) * LQ + l] = pk(s);
}

__global__ void convprep_kernel(const float* __restrict__ cw) {
    int idx = blockIdx.x * 256 + threadIdx.x;   // 16384
    g_convpk[idx] = pk(cw[idx]);
}

// ---------------------------------------------------------------------------
// Lifting -> packed h
// ---------------------------------------------------------------------------
__global__ void lift_kernel(const float* __restrict__ x,
                            const float* __restrict__ Pw,
                            const float* __restrict__ Pb,
                            uint32_t* __restrict__ hpk) {
    int idx = blockIdx.x * 256 + threadIdx.x;
    int l = idx & (LQ - 1);
    int w = (idx >> 13) & 63;
    int b = idx >> 19;
    float x0 = x[(b * 2 + 0) * LQ + l];
    float x1 = x[(b * 2 + 1) * LQ + l];
    hpk[idx] = pk(Pw[2 * w] * x0 + Pw[2 * w + 1] * x1 + Pb[w]);
}

// ---------------------------------------------------------------------------
// Forward DFT with half-period folding (reads packed h).
// ---------------------------------------------------------------------------
__global__ void __launch_bounds__(128) fwd_dft_kernel(const uint32_t* __restrict__ hpk) {
    __shared__ float Es[64 * 65];
    __shared__ float Os[64 * 65];
    __shared__ __align__(16) float Tt[64 * 32];
    int b = blockIdx.x;
    int ks = blockIdx.y;
    int t = threadIdx.x;
    int cc = t & 31;
    int nq = (t >> 5) << 3;
    float acc0[8] = {0.f,0.f,0.f,0.f,0.f,0.f,0.f,0.f};
    float acc1[8] = {0.f,0.f,0.f,0.f,0.f,0.f,0.f,0.f};
    const int lbase = ks * (LH / KSPL);  // 256

    for (int chk = 0; chk < 4; chk++) {
        int l0 = lbase + chk * 64;
        __syncthreads();
#pragma unroll
        for (int j = 0; j < 32; j++) {
            int idx = t + 128 * j;
            int c = idx >> 6, l = idx & 63;
            const uint32_t* hp = hpk + (size_t)(b * 64 + c) * LQ + l0 + l;
            float v1 = upk(hp[0]);
            float v2 = upk(hp[LH]);
            Es[c * 65 + l] = v1 + v2;
            Os[c * 65 + l] = v1 - v2;
        }
#pragma unroll
        for (int j = 0; j < 4; j++) {
            int idx = t + 128 * j;
            ((float4*)Tt)[idx] = ((const float4*)g_T)[l0 * 8 + idx];
        }
        __syncthreads();
#pragma unroll 4
        for (int l = 0; l < 64; l++) {
            float e0 = Es[cc * 65 + l];
            float e1 = Es[(cc + 32) * 65 + l];
            float o0 = Os[cc * 65 + l];
            float o1 = Os[(cc + 32) * 65 + l];
            float4 bv0 = *(float4*)(Tt + l * 32 + nq);
            float4 bv1 = *(float4*)(Tt + l * 32 + nq + 4);
            acc0[0] += e0 * bv0.x; acc0[1] += e0 * bv0.y;
            acc0[2] += o0 * bv0.z; acc0[3] += o0 * bv0.w;
            acc0[4] += e0 * bv1.x; acc0[5] += e0 * bv1.y;
            acc0[6] += o0 * bv1.z; acc0[7] += o0 * bv1.w;
            acc1[0] += e1 * bv0.x; acc1[1] += e1 * bv0.y;
            acc1[2] += o1 * bv0.z; acc1[3] += o1 * bv0.w;
            acc1[4] += e1 * bv1.x; acc1[5] += e1 * bv1.y;
            acc1[6] += o1 * bv1.z; acc1[7] += o1 * bv1.w;
        }
    }
#pragma unroll
    for (int j = 0; j < 8; j++) {
        int n = nq + j;
        size_t base = ((size_t)(b * NBQ + n) * KSPL + ks) * 64;
        g_Fpart[base + cc]      = acc0[j];
        g_Fpart[base + cc + 32] = acc1[j];
    }
}

// ---------------------------------------------------------------------------
// Mode mixing -> packed coefficients.
// ---------------------------------------------------------------------------
__global__ void __launch_bounds__(256) mode_mix_kernel(const float* __restrict__ kwr,
                                                       const float* __restrict__ kwi, int ib) {
    int k = blockIdx.x;
    int bg = blockIdx.y;
    int t = threadIdx.x;
    int o = t & 63;
    int bb = t >> 6;
    int b = bg * 4 + bb;
    __shared__ float wrS[64 * 65], wiS[64 * 65];
    __shared__ float HrS[4][64], HsS[4][64];

    const float* wrG = kwr + ((size_t)ib * 16 + k) * 4096;
    const float* wiG = kwi + ((size_t)ib * 16 + k) * 4096;
#pragma unroll
    for (int j = 0; j < 16; j++) {
        int idx = t + 256 * j;
        int row = idx >> 6, col = idx & 63;
        wrS[row * 65 + col] = wrG[idx];
        wiS[row * 65 + col] = wiG[idx];
    }

    float hr = 0.f, hs = 0.f;
    const float* fr = g_Fpart + (size_t)(b * NBQ + 2 * k) * KSPL * 64;
    const float* fs = g_Fpart + (size_t)(b * NBQ + 2 * k + 1) * KSPL * 64;
#pragma unroll
    for (int p = 0; p < KSPL; p++) {
        hr += fr[p * 64 + o];
        hs += fs[p * 64 + o];
    }
    HrS[bb][o] = hr;
    HsS[bb][o] = hs;
    __syncthreads();

    float ar = 0.f, ai = 0.f;
#pragma unroll 8
    for (int i = 0; i < 64; i++) {
        float xr = HrS[bb][i];
        float xi = -HsS[bb][i];
        float wrv = wrS[o * 65 + i];
        float wiv = wiS[o * 65 + i];
        ar += wrv * xr - wiv * xi;
        ai += wrv * xi + wiv * xr;
    }
    const float invL = 1.0f / (float)LQ;
    float cC, cS;
    if (k == 0) { cC = ar * invL;        cS = 0.f; }
    else        { cC = 2.f * ar * invL;  cS = -2.f * ai * invL; }
    g_coefpk[(b * 64 + o) * NBQ + 2 * k]     = pk(cC);
    g_coefpk[(b * 64 + o) * NBQ + 2 * k + 1] = pk(cS);
}

// ---------------------------------------------------------------------------
// Fused block via mma.sync bf16-split:
//   D[128 l, 64 o] = A[l, K=192] x B[o, K=192]^T, passes over B_hi and B_lo.
// A k-slots (2c, 2c+1) = (a_hi, a_lo): the packed uint32 stores directly.
// B_hi slots (2c,2c+1) = (wh, wh); B_lo = (wl, wl). Sum of both passes
// = (ah+al)(wh+wl), fp32 accumulation -> ~1e-5 rel err.
// 8 warps: wm=wid>>1 owns 32 l, wn=wid&1 owns 32 o. 32 fp32 acc/warp.
// Epilogue: frags -> smem D[o][129] -> bias + exact GELU -> packed store
// (or fused Q-projection when LAST).
// ---------------------------------------------------------------------------
template <bool LAST>
__global__ void __launch_bounds__(256) fused_mma_kernel(
    const uint32_t* __restrict__ hin, uint32_t* __restrict__ hout,
    const float* __restrict__ cb, int ib,
    const float* __restrict__ Qw, const float* __restrict__ Qb,
    float* __restrict__ outp) {
    extern __shared__ __align__(16) char smem[];
    char* Asm = smem + OFF_A;
    int b = blockIdx.y;
    int t = threadIdx.x;
    int wid = t >> 5;
    int lane = t & 31;
    int l0 = blockIdx.x * 128;

    // ---- A build: 128 l x 96 ch; packed u32 -> k-slots (2c, 2c+1) -------
    const uint32_t* hsrc = hin + (size_t)b * 64 * LQ;
#pragma unroll
    for (int j = 0; j < 48; j++) {
        int id = t + 256 * j;            // 12288 = 96 ch x 128 l
        int c = id >> 7;
        int l = id & 127;
        const uint32_t* src = (c < 32) ? (g_Tpk + (size_t)c * LQ)
                                       : (hsrc + (size_t)(c - 32) * LQ);
        uint32_t u = src[l0 + l];
        *(uint32_t*)(Asm + l * AS_B + c * 4) = u;   // conflict-free (101 mod 32 = 5)
    }
    // ---- B build: 64 o x 96 c -> (wh,wh) and (wl,wl) pairs --------------
#pragma unroll
    for (int j = 0; j < 24; j++) {
        int id = t + 256 * j;            // 6144 = 64 o x 96 c
        int o = id / 96;
        int c = id - o * 96;
        uint32_t u = (c < 32) ? g_coefpk[((size_t)b * 64 + o) * NBQ + c]
                              : g_convpk[ib * 4096 + o * 64 + (c - 32)];
        uint32_t wh = u & 0xFFFFu;
        uint32_t wl = u >> 16;
        *(uint32_t*)(smem + OFF_BHI + o * AS_B + c * 4) = wh | (wh << 16);
        *(uint32_t*)(smem + OFF_BLO + o * AS_B + c * 4) = wl | (wl << 16);
    }
    __syncthreads();

    // ---- MMA mainloop ---------------------------------------------------
    int wm = wid >> 1;                   // 0..3 -> l rows [wm*32, +32)
    int wn = wid & 1;                    // 0..1 -> o cols [wn*32, +32)
    int r = lane >> 2;                   // 0..7
    int q = lane & 3;                    // 0..3
    float d[2][4][4];
#pragma unroll
    for (int mi = 0; mi < 2; mi++)
#pragma unroll
        for (int ni = 0; ni < 4; ni++)
#pragma unroll
            for (int e = 0; e < 4; e++) d[mi][ni][e] = 0.f;

#pragma unroll
    for (int ks = 0; ks < 12; ks++) {
        int kb = (ks * 16 + q * 2) * 2;  // byte offset of this thread's k pair
        uint32_t a[2][4];
#pragma unroll
        for (int mi = 0; mi < 2; mi++) {
            const char* arow = Asm + (wm * 32 + mi * 16 + r) * AS_B + kb;
            a[mi][0] = *(const uint32_t*)(arow);
            a[mi][1] = *(const uint32_t*)(arow + 8 * AS_B);
            a[mi][2] = *(const uint32_t*)(arow + 16);
            a[mi][3] = *(const uint32_t*)(arow + 8 * AS_B + 16);
        }
#pragma unroll
        for (int pass = 0; pass < 2; pass++) {
            const char* Bp = smem + (pass ? OFF_BLO : OFF_BHI);
#pragma unroll
            for (int ni = 0; ni < 4; ni++) {
                const char* brow = Bp + (wn * 32 + ni * 8 + r) * AS_B + kb;
                uint32_t b0 = *(const uint32_t*)(brow);
                uint32_t b1 = *(const uint32_t*)(brow + 16);
                mma16816(d[0][ni], a[0], b0, b1);
                mma16816(d[1][ni], a[1], b0, b1);
            }
        }
    }

    // ---- stage D fragments to smem (reuse A region) ---------------------
    __syncthreads();                     // everyone done reading A/B
    float* D = (float*)Asm;              // D[o][129], 64*129*4 = 33024 B
#pragma unroll
    for (int mi = 0; mi < 2; mi++)
#pragma unroll
        for (int ni = 0; ni < 4; ni++) {
            int l = wm * 32 + mi * 16 + r;
            int o = wn * 32 + ni * 8 + q * 2;
            D[o * 129 + l]           = d[mi][ni][0];
            D[(o + 1) * 129 + l]     = d[mi][ni][1];
            D[o * 129 + l + 8]       = d[mi][ni][2];
            D[(o + 1) * 129 + l + 8] = d[mi][ni][3];
        }
    __syncthreads();

    // ---- epilogue -------------------------------------------------------
    if (!LAST) {
#pragma unroll
        for (int j = 0; j < 32; j++) {
            int idx = t + 256 * j;       // 8192 = 64 o x 128 l
            int o = idx >> 7;
            int l = idx & 127;
            float v = D[o * 129 + l] + __ldg(&cb[ib * 64 + o]);
            hout[((size_t)b * 64 + o) * LQ + l0 + l] = pk(gelu_exact(v));
        }
    } else {
        float* partS = (float*)(smem + OFF_BHI);   // 2 x 128 floats
        int l = t & 127;
        int ob = t >> 7;                 // 0 or 1
        float s = 0.f;
#pragma unroll
        for (int j = 0; j < 32; j++) {
            int o = ob + 2 * j;
            float v = D[o * 129 + l] + __ldg(&cb[ib * 64 + o]);
            s += __ldg(&Qw[o]) * gelu_exact(v);
        }
        partS[ob * 128 + l] = s;
        __syncthreads();
        if (t < 128)
            outp[(size_t)b * LQ + l0 + t] = partS[t] + partS[128 + t] + __ldg(&Qb[0]);
    }
}

// ---------------------------------------------------------------------------
extern "C" void kernel_launch(void* const* d_in, const int* in_sizes, int n_in,
                              void* d_out, int out_size) {
    const float* x   = (const float*)d_in[0];
    const float* Pw  = (const float*)d_in[1];
    const float* Pb  = (const float*)d_in[2];
    const float* kwr = (const float*)d_in[3];
    const float* kwi = (const float*)d_in[4];
    const float* cw  = (const float*)d_in[5];
    const float* cb  = (const float*)d_in[6];
    const float* Qw  = (const float*)d_in[7];
    const float* Qb  = (const float*)d_in[8];
    float* out = (float*)d_out;

    uint32_t *hA = nullptr, *hB = nullptr;
    cudaGetSymbolAddress((void**)&hA, g_hpkA);
    cudaGetSymbolAddress((void**)&hB, g_hpkB);

    cudaFuncSetAttribute(fused_mma_kernel<false>,
                         cudaFuncAttributeMaxDynamicSharedMemorySize, FUSED_SMEM);
    cudaFuncSetAttribute(fused_mma_kernel<true>,
                         cudaFuncAttributeMaxDynamicSharedMemorySize, FUSED_SMEM);

    build_table_kernel<<<(LQ * MQ) / 256, 256>>>();
    convprep_kernel<<<64, 256>>>(cw);
    lift_kernel<<<(BQ * WQ * LQ) / 256, 256>>>(x, Pw, Pb, hA);

    uint32_t* cur = hA;
    uint32_t* nxt = hB;
    for (int ib = 0; ib < 4; ib++) {
        fwd_dft_kernel<<<dim3(BQ, KSPL), 128>>>(cur);
        mode_mix_kernel<<<dim3(16, 8), 256>>>(kwr, kwi, ib);
        if (ib < 3) {
            fused_mma_kernel<false><<<dim3(LQ / 128, BQ), 256, FUSED_SMEM>>>(
                cur, nxt, cb, ib, Qw, Qb, out);
        } else {
            fused_mma_kernel<true><<<dim3(LQ / 128, BQ), 256, FUSED_SMEM>>>(
                cur, nxt, cb, ib, Qw, Qb, out);
        }
        uint32_t* tmp = cur; cur = nxt; nxt = tmp;
    }
}